// round 9
// baseline (speedup 1.0000x reference)
#include <cuda_runtime.h>
#include <cuda_bf16.h>
#include <math.h>
#include <stdint.h>

#define BB 256
#define LL 256
#define VV 14
#define EMBD 512
#define HH 128
#define OC 256
#define NP 196
#define NPP 256
#define KLIN 32768
#define NJ 128
#define SPLITK 64
#define KC (KLIN/SPLITK)   // 512 -> 4 conv channels per CTA

typedef unsigned long long ull;

// dynamic smem layout for k_gemmW (bytes)
#define PLSTRIDE 18432     // 128 rows x 144B (72 bf16, padded)
#define A_OFF    0         // 3 planes
#define B_OFF    55296     // 3 planes
#define STG_OFF  110592    // 64 x 130 fp32 = 33280
#define P2_OFF   143872    // 3072 fp32 = 12288
#define SPI_OFF  156160    // 128 x 132 uchar = 16896
#define BIAS_OFF 173056    // 16
#define W_TOTAL  173072

__device__ float g_poolT_e[EMBD*NPP];
__device__ float g_poolT_f[EMBD*NPP];
__device__ float g_pbpart[4*2*3*OC*NPP];
__device__ float g_P2[2*3*OC*NPP];
__device__ unsigned char g_pi8T[2*HH*BB];
__device__ float g_partial[SPLITK*BB*NJ];
__device__ float g_vec[BB*NJ];
__device__ float g_r[3*BB*64];
__device__ float g_Wsum[3*64*128];
__device__ float g_Lmid[64*256];
__device__ int   g_tok[BB*256];

__device__ __forceinline__ ull pk2(float lo, float hi){
    ull r; asm("mov.b64 %0, {%1, %2};" : "=l"(r) : "f"(lo), "f"(hi)); return r;
}
__device__ __forceinline__ void ffma2(ull& c, ull a, ull b){
    asm("fma.rn.f32x2 %0, %1, %2, %0;" : "+l"(c) : "l"(a), "l"(b));
}
__device__ __forceinline__ uint32_t smem_u32(const void* p){
    uint32_t a;
    asm("{ .reg .u64 t; cvta.to.shared.u64 t, %1; cvt.u32.u64 %0, t; }" : "=r"(a) : "l"(p));
    return a;
}
__device__ __forceinline__ void ldm4(uint32_t* r, uint32_t addr){
    asm volatile("ldmatrix.sync.aligned.m8n8.x4.shared.b16 {%0,%1,%2,%3}, [%4];"
        : "=r"(r[0]), "=r"(r[1]), "=r"(r[2]), "=r"(r[3]) : "r"(addr));
}
__device__ __forceinline__ void mma16816(float* c, const uint32_t* a, uint32_t b0, uint32_t b1){
    asm volatile("mma.sync.aligned.m16n8k16.row.col.f32.bf16.bf16.f32 "
        "{%0,%1,%2,%3}, {%4,%5,%6,%7}, {%8,%9}, {%0,%1,%2,%3};"
        : "+f"(c[0]), "+f"(c[1]), "+f"(c[2]), "+f"(c[3])
        : "r"(a[0]), "r"(a[1]), "r"(a[2]), "r"(a[3]), "r"(b0), "r"(b1));
}
__device__ __forceinline__ void bsplit(float v, uint16_t& h, uint16_t& m, uint16_t& l){
    __nv_bfloat16 b0 = __float2bfloat16_rn(v);
    float r1 = v - __bfloat162float(b0);
    __nv_bfloat16 b1 = __float2bfloat16_rn(r1);
    float r2 = r1 - __bfloat162float(b1);
    __nv_bfloat16 b2 = __float2bfloat16_rn(r2);
    h = __bfloat16_as_ushort(b0); m = __bfloat16_as_ushort(b1); l = __bfloat16_as_ushort(b2);
}

__global__ void k_poolT2(const float* __restrict__ eemb, const float* __restrict__ femb){
    int idx = blockIdx.x*256 + threadIdx.x;
    int br = idx / (EMBD*NPP), r = idx % (EMBD*NPP);
    int c = r >> 8, p = r & 255;
    const float* emb = br ? femb : eemb;
    float v = 0.f;
    if (p < NP){
        int t1 = p / VV, t2 = p % VV;
        v = fmaxf(emb[t1*EMBD + c], emb[t2*EMBD + c]);
    }
    (br ? g_poolT_f : g_poolT_e)[c*NPP + p] = v;
}

__global__ __launch_bounds__(512) void k_pbuild2(const float* __restrict__ ecw,
                                                 const float* __restrict__ fcw){
    int ot = blockIdx.x, cs = blockIdx.y, br = blockIdx.z;
    const float* cw    = br ? fcw : ecw;
    const float* poolT = br ? g_poolT_f : g_poolT_e;
    int o0 = ot*8, c0 = cs*128;
    __shared__ float ws[8*3*128];
    int tid = threadIdx.x;
    for (int e = tid; e < 3072; e += 512){
        int oi = e / 384, r = e % 384, kh = r >> 7, c = r & 127;
        ws[e] = cw[((size_t)(o0+oi)*EMBD + (c0+c))*9 + 1 + kh*3];
    }
    __syncthreads();
    int pg = tid & 63, oi = tid >> 6, p0 = pg*4;
    ull a0=0,a1=0,a2=0,a3=0,a4=0,a5=0;
    const float* pt  = poolT + (size_t)c0*NPP + p0;
    const float* wsp = ws + oi*384;
    #pragma unroll 4
    for (int c = 0; c < 128; c++){
        float4 pv = *(const float4*)(pt + (size_t)c*NPP);
        ull pa0 = pk2(pv.x, pv.y), pa1 = pk2(pv.z, pv.w);
        float w0 = wsp[c], w1 = wsp[128+c], w2 = wsp[256+c];
        ull b0 = pk2(w0,w0), b1 = pk2(w1,w1), b2 = pk2(w2,w2);
        ffma2(a0, pa0, b0); ffma2(a1, pa1, b0);
        ffma2(a2, pa0, b1); ffma2(a3, pa1, b1);
        ffma2(a4, pa0, b2); ffma2(a5, pa1, b2);
    }
    size_t base = (((size_t)(cs*2 + br)*3)*OC + (o0+oi))*NPP + p0;
    *(ulonglong2*)(g_pbpart + base)            = make_ulonglong2(a0, a1);
    *(ulonglong2*)(g_pbpart + base + OC*NPP)   = make_ulonglong2(a2, a3);
    *(ulonglong2*)(g_pbpart + base + 2*OC*NPP) = make_ulonglong2(a4, a5);
}

__global__ void k_pbreduce(){
    int idx = blockIdx.x*256 + threadIdx.x;
    int br = idx / (3*OC*NPP), inner = idx % (3*OC*NPP);
    float s = g_pbpart[(0*2+br)*(3*OC*NPP) + inner]
            + g_pbpart[(1*2+br)*(3*OC*NPP) + inner]
            + g_pbpart[(2*2+br)*(3*OC*NPP) + inner]
            + g_pbpart[(3*2+br)*(3*OC*NPP) + inner];
    g_P2[idx] = s;
}

__global__ void k_pairidx8(int which, const int* __restrict__ x){
    int idx = blockIdx.x*256 + threadIdx.x;
    int b = idx & 255, h = idx >> 8;
    const int* tok = which ? g_tok : x;
    g_pi8T[which*HH*BB + idx] =
        (unsigned char)(tok[b*LL + 2*h]*VV + tok[b*LL + 2*h + 1]);
}

// ---- warp-MMA fused conv+GEMM: grid (2,64), 256 threads (8 warps 4x2) ------
// D[128m x 128j] partial for K-chunk KC=512, exact 3-way bf16 split, 6 products.
__global__ __launch_bounds__(256) void k_gemmW(int which, const float* __restrict__ W,
                                               const float* __restrict__ bias){
    extern __shared__ char dyn[];
    const int tid = threadIdx.x;
    const int wid = tid >> 5, lane = tid & 31;
    const int m0 = blockIdx.x * 128;
    const int kz = blockIdx.y;
    const int k0 = kz * KC;
    const int oF = k0 >> 7;
    const uint32_t sbase = smem_u32(dyn);

    float* sP2   = (float*)(dyn + P2_OFF);
    unsigned char (*spi)[132] = (unsigned char(*)[132])(dyn + SPI_OFF);
    float* sbias = (float*)(dyn + BIAS_OFF);
    float* stg   = (float*)(dyn + STG_OFF);     // [k][130]

    const float* P2 = g_P2 + (size_t)which*(3*OC*NPP);
    for (int e = tid; e < 3072; e += 256){
        int oi = e / 768, r = e % 768;
        sP2[e] = P2[(size_t)(r >> 8)*OC*NPP + (oF + oi)*NPP + (r & 255)];
    }
    const unsigned char* piT = g_pi8T + (size_t)which*(HH*BB);
    for (int e = tid; e < 4096; e += 256){
        int h = e >> 5, g = e & 31;
        *(uchar4*)&spi[h][g*4] = *(const uchar4*)(piT + h*BB + m0 + g*4);
    }
    if (tid < 4) sbias[tid] = bias[oF + tid];
    __syncthreads();

    const int mBase = (wid >> 1) * 32;
    const int nBase = (wid & 1) * 64;
    float acc[2][8][4];
    #pragma unroll
    for (int i=0;i<2;i++)
        #pragma unroll
        for (int j=0;j<8;j++)
            #pragma unroll
            for (int q=0;q<4;q++) acc[i][j][q] = 0.f;

    const int rowT = tid & 127;     // m or n row this thread builds
    const int khT  = tid >> 7;      // 0/1 -> k half (32 each)

    for (int t = 0; t < 8; t++){
        int kt = k0 + t*64;
        // phase 1: stage W (coalesced) ---------------------------------------
        for (int e = tid; e < 8192; e += 256){
            int k = e >> 7, n = e & 127;
            stg[k*130 + n] = W[(size_t)(kt + k)*NJ + n];
        }
        // A build: conv from LUT -> 3 bf16 planes [m][72] --------------------
        {
            int oi = t >> 1, h0 = (t & 1) * 64;
            const float* pa = sP2 + oi*768;
            float vb = sbias[oi];
            char* baseA = dyn + A_OFF + rowT*144 + khT*64;
            #pragma unroll 4
            for (int ip = 0; ip < 16; ip++){
                uint16_t h0a,m0a,l0a,h1a,m1a,l1a;
                #pragma unroll
                for (int e2 = 0; e2 < 2; e2++){
                    int h = h0 + khT*32 + ip*2 + e2;
                    float v = vb;
                    if (h > 0)   v += pa[(int)spi[h-1][rowT]];
                    v += pa[256 + (int)spi[h][rowT]];
                    if (h < 127) v += pa[512 + (int)spi[h+1][rowT]];
                    if (e2){ bsplit(v, h1a, m1a, l1a); } else { bsplit(v, h0a, m0a, l0a); }
                }
                uint32_t ph = (uint32_t)h0a | ((uint32_t)h1a << 16);
                uint32_t pm = (uint32_t)m0a | ((uint32_t)m1a << 16);
                uint32_t pl = (uint32_t)l0a | ((uint32_t)l1a << 16);
                *(uint32_t*)(baseA + ip*4)              = ph;
                *(uint32_t*)(baseA + PLSTRIDE + ip*4)   = pm;
                *(uint32_t*)(baseA + 2*PLSTRIDE + ip*4) = pl;
            }
        }
        __syncthreads();
        // phase 2: B build: Bs[n][k] = W[kt+k][n] -> 3 bf16 planes -----------
        {
            char* baseB = dyn + B_OFF + rowT*144 + khT*64;
            #pragma unroll 4
            for (int ip = 0; ip < 16; ip++){
                int k = khT*32 + ip*2;
                float v0 = stg[k*130 + rowT];
                float v1 = stg[(k+1)*130 + rowT];
                uint16_t h0b,m0b,l0b,h1b,m1b,l1b;
                bsplit(v0, h0b, m0b, l0b);
                bsplit(v1, h1b, m1b, l1b);
                *(uint32_t*)(baseB + ip*4)              = (uint32_t)h0b | ((uint32_t)h1b << 16);
                *(uint32_t*)(baseB + PLSTRIDE + ip*4)   = (uint32_t)m0b | ((uint32_t)m1b << 16);
                *(uint32_t*)(baseB + 2*PLSTRIDE + ip*4) = (uint32_t)l0b | ((uint32_t)l1b << 16);
            }
        }
        __syncthreads();
        // phase 3: warp MMA ---------------------------------------------------
        #pragma unroll
        for (int s = 0; s < 4; s++){
            int kB = s*16;
            uint32_t aF[3][2][4];
            uint32_t aRow = (uint32_t)(mBase + (lane & 15));
            uint32_t aColB = (uint32_t)((kB + ((lane & 16) ? 8 : 0)) * 2);
            #pragma unroll
            for (int p = 0; p < 3; p++)
                #pragma unroll
                for (int mt = 0; mt < 2; mt++)
                    ldm4(aF[p][mt], sbase + A_OFF + p*PLSTRIDE + (aRow + mt*16)*144 + aColB);
            #pragma unroll
            for (int np = 0; np < 4; np++){
                uint32_t bF[3][4];
                uint32_t nRow = (uint32_t)(nBase + np*16 + (lane & 7) + ((lane & 16) ? 8 : 0));
                uint32_t bColB = (uint32_t)((kB + ((lane & 8) ? 8 : 0)) * 2);
                #pragma unroll
                for (int q = 0; q < 3; q++)
                    ldm4(bF[q], sbase + B_OFF + q*PLSTRIDE + nRow*144 + bColB);
                // 6 split products: hh, hm, mh, mm, hl, lh
                #pragma unroll
                for (int mt = 0; mt < 2; mt++){
                    float* c0 = acc[mt][np*2];
                    float* c1 = acc[mt][np*2 + 1];
                    mma16816(c0, aF[0][mt], bF[0][0], bF[0][1]);
                    mma16816(c1, aF[0][mt], bF[0][2], bF[0][3]);
                    mma16816(c0, aF[0][mt], bF[1][0], bF[1][1]);
                    mma16816(c1, aF[0][mt], bF[1][2], bF[1][3]);
                    mma16816(c0, aF[1][mt], bF[0][0], bF[0][1]);
                    mma16816(c1, aF[1][mt], bF[0][2], bF[0][3]);
                    mma16816(c0, aF[1][mt], bF[1][0], bF[1][1]);
                    mma16816(c1, aF[1][mt], bF[1][2], bF[1][3]);
                    mma16816(c0, aF[0][mt], bF[2][0], bF[2][1]);
                    mma16816(c1, aF[0][mt], bF[2][2], bF[2][3]);
                    mma16816(c0, aF[2][mt], bF[0][0], bF[0][1]);
                    mma16816(c1, aF[2][mt], bF[0][2], bF[0][3]);
                }
            }
        }
        __syncthreads();
    }

    // epilogue: direct partial writes
    float* outp = g_partial + (size_t)kz*(BB*NJ);
    int gr = lane >> 2, gc = (lane & 3)*2;
    #pragma unroll
    for (int mt = 0; mt < 2; mt++){
        #pragma unroll
        for (int nt = 0; nt < 8; nt++){
            int row = m0 + mBase + mt*16 + gr;
            int col = nBase + nt*8 + gc;
            float* c = acc[mt][nt];
            *(float2*)&outp[(size_t)row*NJ + col]     = make_float2(c[0], c[1]);
            *(float2*)&outp[(size_t)(row+8)*NJ + col] = make_float2(c[2], c[3]);
        }
    }
}

__global__ void k_redsm(const float* __restrict__ bias){
    __shared__ float red[128];
    int b = blockIdx.x, t = threadIdx.x;
    float s = bias[t];
    #pragma unroll 8
    for (int kz=0; kz<SPLITK; kz++) s += g_partial[(size_t)(kz*BB + b)*NJ + t];
    float v = s;
    red[t] = v; __syncthreads();
    for (int st=64; st; st>>=1){ if (t < st) red[t] = fmaxf(red[t], red[t+st]); __syncthreads(); }
    float mx = red[0]; __syncthreads();
    float e = expf(v - mx);
    red[t] = e; __syncthreads();
    for (int st=64; st; st>>=1){ if (t < st) red[t] += red[t+st]; __syncthreads(); }
    g_vec[b*128 + t] = e / red[0];
}

__global__ void k_wsum(const float* __restrict__ mcw){
    int idx = blockIdx.x*256 + threadIdx.x;
    if (idx >= 3*64*128) return;
    int v = idx / 8192, rem = idx % 8192, base = rem*9 + 1;
    float w0 = mcw[base], w1 = mcw[base+3], w2 = mcw[base+6];
    g_Wsum[idx] = (v==0) ? (w1+w2) : (v==1) ? (w0+w1+w2) : (w0+w1);
}

__global__ void k_rgemm(const float* __restrict__ mcb){
    int idx = blockIdx.x*256 + threadIdx.x;
    if (idx >= 3*BB*64) return;
    int v = idx / (BB*64), rem = idx % (BB*64);
    int b = rem / 64, o = rem % 64;
    const float* eo = g_vec + b*128;
    const float* ws = g_Wsum + v*8192 + o*128;
    float s = mcb[o];
    for (int c=0;c<128;c++) s = fmaf(eo[c], ws[c], s);
    g_r[idx] = fmaxf(s, 0.f);
}

__global__ void k_lmid(const float* __restrict__ mlw){
    int idx = blockIdx.x*256 + threadIdx.x;
    if (idx >= 64*256) return;
    int o = idx >> 8, j = idx & 255;
    float s = 0.f;
    for (int h=1; h<127; h++) s += mlw[(size_t)(o*128 + h)*256 + j];
    g_Lmid[idx] = s;
}

__global__ void k_mtok(const float* __restrict__ mlw, const float* __restrict__ mlb){
    int idx = blockIdx.x*256 + threadIdx.x;
    if (idx >= BB*256) return;
    int b = idx >> 8, j = idx & 255;
    const float* r0   = g_r + 0*BB*64 + b*64;
    const float* ri   = g_r + 1*BB*64 + b*64;
    const float* r127 = g_r + 2*BB*64 + b*64;
    float s = mlb[j];
    for (int o=0; o<64; o++){
        s = fmaf(r0[o],   mlw[(size_t)o*32768 + j],          s);
        s = fmaf(ri[o],   g_Lmid[o*256 + j],                 s);
        s = fmaf(r127[o], mlw[(size_t)o*32768 + 32512 + j],  s);
    }
    int t = (int)floorf(fabsf(s) * 100.0f);
    g_tok[idx] = t % VV;
}

__global__ void k_redlin2(const float* __restrict__ bias, const float* __restrict__ w2,
                          const float* __restrict__ b2, float* __restrict__ out){
    __shared__ float f[128];
    int b = blockIdx.x, t = threadIdx.x;
    float s = bias[t];
    #pragma unroll 8
    for (int kz=0; kz<SPLITK; kz++) s += g_partial[(size_t)(kz*BB + b)*NJ + t];
    f[t] = s; __syncthreads();
    if (t < 32){
        float logit = -INFINITY;
        if (t < VV){
            logit = b2[t];
            for (int j=0; j<128; j++) logit = fmaf(f[j], w2[j*VV + t], logit);
        }
        float mx = logit;
        for (int off=16; off; off>>=1) mx = fmaxf(mx, __shfl_xor_sync(0xffffffffu, mx, off));
        float e = (t < VV) ? expf(logit - mx) : 0.f;
        float sm = e;
        for (int off=16; off; off>>=1) sm += __shfl_xor_sync(0xffffffffu, sm, off);
        if (t < VV) out[b*VV + t] = e / sm;
    }
}

extern "C" void kernel_launch(void* const* d_in, const int* in_sizes, int n_in,
                              void* d_out, int out_size){
    const int*   x    = (const int*)  d_in[0];
    const float* eemb = (const float*)d_in[1];
    const float* ecw  = (const float*)d_in[2];
    const float* ecb  = (const float*)d_in[3];
    const float* elw  = (const float*)d_in[4];
    const float* elb  = (const float*)d_in[5];
    const float* mcw  = (const float*)d_in[7];
    const float* mcb  = (const float*)d_in[8];
    const float* mlw  = (const float*)d_in[9];
    const float* mlb  = (const float*)d_in[10];
    const float* femb = (const float*)d_in[11];
    const float* fcw  = (const float*)d_in[12];
    const float* fcb  = (const float*)d_in[13];
    const float* flw1 = (const float*)d_in[14];
    const float* flb1 = (const float*)d_in[15];
    const float* flw2 = (const float*)d_in[16];
    const float* flb2 = (const float*)d_in[17];
    float* out = (float*)d_out;

    cudaFuncSetAttribute(k_gemmW, cudaFuncAttributeMaxDynamicSharedMemorySize, W_TOTAL);

    k_poolT2<<<(2*EMBD*NPP)/256, 256>>>(eemb, femb);
    k_pbuild2<<<dim3(32,4,2), 512>>>(ecw, fcw);
    k_pbreduce<<<(2*3*OC*NPP)/256, 256>>>();
    k_pairidx8<<<(HH*BB)/256, 256>>>(0, x);

    k_gemmW<<<dim3(2, SPLITK), 256, W_TOTAL>>>(0, elw, ecb);
    k_redsm<<<BB, 128>>>(elb);

    k_wsum<<<(3*64*128)/256, 256>>>(mcw);
    k_rgemm<<<(3*BB*64)/256, 256>>>(mcb);
    k_lmid<<<(64*256)/256, 256>>>(mlw);
    k_mtok<<<(BB*256)/256, 256>>>(mlw, mlb);
    k_pairidx8<<<(HH*BB)/256, 256>>>(1, x);

    k_gemmW<<<dim3(2, SPLITK), 256, W_TOTAL>>>(1, flw1, fcb);
    k_redlin2<<<BB, 128>>>(flb1, flw2, flb2, out);
}